// round 3
// baseline (speedup 1.0000x reference)
#include <cuda_runtime.h>
#include <cuda_bf16.h>
#include <cstdint>

#define N_NODES 50000
#define IN_F 128
#define OUT_F 128
#define N_EDGES 800000
#define ALPHA 0.2f
#define EPS 1e-16f

// ---------------- device scratch (static, no allocation) ----------------
__device__ __align__(16) float g_Wh[(size_t)N_NODES * OUT_F];   // 25.6 MB
__device__ float g_s1[N_NODES];
__device__ float g_s2[N_NODES];
__device__ int   g_cnt[N_NODES];
__device__ int   g_rowptr[N_NODES + 1];
__device__ int   g_cursor[N_NODES];
__device__ float g_se[N_EDGES];     // sorted-by-row leaky-relu scores
__device__ int   g_scol[N_EDGES];   // sorted-by-row col indices

// ---------------- f32x2 packed helpers ----------------
__device__ __forceinline__ unsigned long long pk2(float lo, float hi) {
    unsigned long long r;
    asm("mov.b64 %0, {%1, %2};" : "=l"(r) : "f"(lo), "f"(hi));
    return r;
}
__device__ __forceinline__ void upk2(unsigned long long p, float& lo, float& hi) {
    asm("mov.b64 {%0, %1}, %2;" : "=f"(lo), "=f"(hi) : "l"(p));
}
__device__ __forceinline__ unsigned long long fma2(unsigned long long a,
                                                   unsigned long long b,
                                                   unsigned long long c) {
    unsigned long long d;
    asm("fma.rn.f32x2 %0, %1, %2, %3;" : "=l"(d) : "l"(a), "l"(b), "l"(c));
    return d;
}

// ---------------- K1: Wh = h @ W (f32x2), fused s1/s2 epilogue ----------------
__global__ __launch_bounds__(256) void gat_gemm_kernel(
    const float* __restrict__ h, const float* __restrict__ W,
    const float* __restrict__ a)
{
    __shared__ float hs[64][36];     // 64 rows x 32 k (padded)
    __shared__ float Ws[32 * 128];   // k-tile x 128 cols

    const int tid = threadIdx.x;
    const int tx = tid & 31;
    const int ty = tid >> 5;
    const int row0 = blockIdx.x * 64;

    unsigned long long acc2[8][2];
#pragma unroll
    for (int r = 0; r < 8; r++) { acc2[r][0] = 0ull; acc2[r][1] = 0ull; }

    for (int kt = 0; kt < IN_F; kt += 32) {
        const float4* Wg = reinterpret_cast<const float4*>(W + kt * OUT_F);
        float4* Wsv = reinterpret_cast<float4*>(Ws);
#pragma unroll
        for (int i = 0; i < 4; i++) Wsv[tid + 256 * i] = Wg[tid + 256 * i];

#pragma unroll
        for (int i = 0; i < 2; i++) {
            int idx = tid + 256 * i;      // 0..511
            int r = idx >> 3;             // 0..63
            int cc = (idx & 7) * 4;       // 0..28
            int gr = row0 + r;
            float4 v = make_float4(0.f, 0.f, 0.f, 0.f);
            if (gr < N_NODES)
                v = *reinterpret_cast<const float4*>(h + (size_t)gr * IN_F + kt + cc);
            *reinterpret_cast<float4*>(&hs[r][cc]) = v;
        }
        __syncthreads();

#pragma unroll
        for (int k = 0; k < 32; k++) {
            float4 w = *reinterpret_cast<const float4*>(Ws + k * 128 + tx * 4);
            unsigned long long w01 = pk2(w.x, w.y);
            unsigned long long w23 = pk2(w.z, w.w);
#pragma unroll
            for (int r = 0; r < 8; r++) {
                float hv = hs[ty * 8 + r][k];
                unsigned long long h2 = pk2(hv, hv);
                acc2[r][0] = fma2(h2, w01, acc2[r][0]);
                acc2[r][1] = fma2(h2, w23, acc2[r][1]);
            }
        }
        __syncthreads();
    }

    float4 a1 = *reinterpret_cast<const float4*>(a + tx * 4);
    float4 a2 = *reinterpret_cast<const float4*>(a + OUT_F + tx * 4);

#pragma unroll
    for (int r = 0; r < 8; r++) {
        int gr = row0 + ty * 8 + r;
        float4 v;
        upk2(acc2[r][0], v.x, v.y);
        upk2(acc2[r][1], v.z, v.w);
        float p1 = v.x * a1.x + v.y * a1.y + v.z * a1.z + v.w * a1.w;
        float p2 = v.x * a2.x + v.y * a2.y + v.z * a2.z + v.w * a2.w;
#pragma unroll
        for (int off = 16; off > 0; off >>= 1) {
            p1 += __shfl_xor_sync(0xFFFFFFFFu, p1, off);
            p2 += __shfl_xor_sync(0xFFFFFFFFu, p2, off);
        }
        if (gr < N_NODES) {
            *reinterpret_cast<float4*>(g_Wh + (size_t)gr * OUT_F + tx * 4) = v;
            if (tx == 0) { g_s1[gr] = p1; g_s2[gr] = p2; }
        }
    }
}

// ---------------- K2: zero histogram ----------------
__global__ void zero_cnt_kernel()
{
    int i = blockIdx.x * blockDim.x + threadIdx.x;
    if (i < N_NODES) g_cnt[i] = 0;
}

// ---------------- K3: histogram of rows ----------------
__global__ __launch_bounds__(256) void hist_kernel(const int* __restrict__ ei)
{
    int i = blockIdx.x * blockDim.x + threadIdx.x;
    if (i >= N_EDGES) return;
    atomicAdd(&g_cnt[ei[i]], 1);
}

// ---------------- K4: single-block exclusive scan -> rowptr + cursor ----------------
__global__ __launch_bounds__(1024) void scan_kernel()
{
    const int C = (N_NODES + 1023) / 1024;  // 49
    int t = threadIdx.x;
    int lo = t * C;
    int hi = min(lo + C, N_NODES);

    int sum = 0;
    for (int i = lo; i < hi; i++) sum += g_cnt[i];

    __shared__ int ssum[1024];
    ssum[t] = sum;
    __syncthreads();

    // inclusive Hillis-Steele scan
    for (int o = 1; o < 1024; o <<= 1) {
        int x = (t >= o) ? ssum[t - o] : 0;
        __syncthreads();
        ssum[t] += x;
        __syncthreads();
    }

    int running = ssum[t] - sum;  // exclusive base
    for (int i = lo; i < hi; i++) {
        g_rowptr[i] = running;
        g_cursor[i] = running;
        running += g_cnt[i];
    }
    if (t == 1023) g_rowptr[N_NODES] = ssum[1023];
}

// ---------------- K5: scatter edges into row-sorted order; compute e ----------------
__global__ __launch_bounds__(256) void scatter_kernel(const int* __restrict__ ei)
{
    int i = blockIdx.x * blockDim.x + threadIdx.x;
    if (i >= N_EDGES) return;
    int r = ei[i];
    int c = ei[N_EDGES + i];
    float e = g_s1[r] + g_s2[c];
    e = (e > 0.0f) ? e : ALPHA * e;
    int pos = atomicAdd(&g_cursor[r], 1);
    g_se[pos] = e;
    g_scol[pos] = c;
}

// ---------------- K6: fused per-row softmax + gather-aggregate (warp per row) ----------------
__global__ __launch_bounds__(256) void row_kernel(float* __restrict__ out)
{
    int r = (blockIdx.x * blockDim.x + threadIdx.x) >> 5;
    if (r >= N_NODES) return;
    int lane = threadIdx.x & 31;
    int start = g_rowptr[r];
    int end   = g_rowptr[r + 1];

    // pass 1: rowsum = sum(e)
    float s = 0.0f;
    for (int j = start + lane; j < end; j += 32) s += g_se[j];
#pragma unroll
    for (int o = 16; o > 0; o >>= 1) s += __shfl_xor_sync(0xFFFFFFFFu, s, o);
    float rowsum = s;

    // pass 2: expsum
    float es = 0.0f;
    for (int j = start + lane; j < end; j += 32) es += __expf(g_se[j] - rowsum);
#pragma unroll
    for (int o = 16; o > 0; o >>= 1) es += __shfl_xor_sync(0xFFFFFFFFu, es, o);
    float inv = 1.0f / (es + EPS);

    // pass 3: gather-aggregate
    float4 acc = make_float4(0.f, 0.f, 0.f, 0.f);
    for (int base = start; base < end; base += 32) {
        int idx = base + lane;
        float att = 0.0f;
        int col = 0;
        if (idx < end) {
            att = __expf(g_se[idx] - rowsum) * inv;
            col = g_scol[idx];
        }
        int m = min(32, end - base);
#pragma unroll 4
        for (int j = 0; j < m; j++) {
            float aj = __shfl_sync(0xFFFFFFFFu, att, j);
            int   cj = __shfl_sync(0xFFFFFFFFu, col, j);
            float4 v = *reinterpret_cast<const float4*>(g_Wh + (size_t)cj * OUT_F + lane * 4);
            acc.x += aj * v.x;
            acc.y += aj * v.y;
            acc.z += aj * v.z;
            acc.w += aj * v.w;
        }
    }
    *reinterpret_cast<float4*>(out + (size_t)r * OUT_F + lane * 4) = acc;
}

// ---------------- launch ----------------
extern "C" void kernel_launch(void* const* d_in, const int* in_sizes, int n_in,
                              void* d_out, int out_size)
{
    const float* h  = (const float*)d_in[0];
    const int*   ei = (const int*)d_in[1];
    const float* W  = (const float*)d_in[2];
    const float* a  = (const float*)d_in[3];
    float* out = (float*)d_out;

    gat_gemm_kernel<<<(N_NODES + 63) / 64, 256>>>(h, W, a);

    zero_cnt_kernel<<<(N_NODES + 255) / 256, 256>>>();
    hist_kernel<<<(N_EDGES + 255) / 256, 256>>>(ei);
    scan_kernel<<<1, 1024>>>();
    scatter_kernel<<<(N_EDGES + 255) / 256, 256>>>(ei);

    row_kernel<<<(N_NODES * 32 + 255) / 256, 256>>>(out);
}

// round 9
// speedup vs baseline: 1.7913x; 1.7913x over previous
#include <cuda_runtime.h>
#include <cuda_fp16.h>
#include <cuda_bf16.h>
#include <cstdint>

#define N_NODES 50000
#define IN_F 128
#define OUT_F 128
#define N_EDGES 800000
#define ALPHA 0.2f
#define EPS 1e-16f

#define SCAN_BLK 256
#define SCAN_NB ((N_NODES + SCAN_BLK - 1) / SCAN_BLK)   // 196

// ---------------- device scratch (static, no allocation) ----------------
__device__ __align__(16) __half g_Wh[(size_t)N_NODES * OUT_F];   // 12.8 MB (fp16)
__device__ float g_s1[N_NODES];
__device__ float g_s2[N_NODES];
__device__ int   g_cnt[N_NODES];
__device__ int   g_bsum[SCAN_NB];
__device__ int   g_bbase[SCAN_NB];
__device__ int   g_rowptr[N_NODES + 1];
__device__ int   g_cursor[N_NODES];
__device__ __align__(8) float2 g_ec[N_EDGES];  // .x = e (lrelu score), .y = bitcast(col)

// ---------------- f32x2 packed helpers ----------------
__device__ __forceinline__ unsigned long long pk2(float lo, float hi) {
    unsigned long long r;
    asm("mov.b64 %0, {%1, %2};" : "=l"(r) : "f"(lo), "f"(hi));
    return r;
}
__device__ __forceinline__ void upk2(unsigned long long p, float& lo, float& hi) {
    asm("mov.b64 {%0, %1}, %2;" : "=f"(lo), "=f"(hi) : "l"(p));
}
__device__ __forceinline__ unsigned long long fma2(unsigned long long a,
                                                   unsigned long long b,
                                                   unsigned long long c) {
    unsigned long long d;
    asm("fma.rn.f32x2 %0, %1, %2, %3;" : "=l"(d) : "l"(a), "l"(b), "l"(c));
    return d;
}

// ---------------- K1: Wh = h @ W (f32x2), fused s1/s2 epilogue, fp16 store ----------------
__global__ __launch_bounds__(256) void gat_gemm_kernel(
    const float* __restrict__ h, const float* __restrict__ W,
    const float* __restrict__ a)
{
    __shared__ float hs[64][36];
    __shared__ float Ws[32 * 128];

    const int tid = threadIdx.x;
    const int tx = tid & 31;
    const int ty = tid >> 5;
    const int row0 = blockIdx.x * 64;

    unsigned long long acc2[8][2];
#pragma unroll
    for (int r = 0; r < 8; r++) { acc2[r][0] = 0ull; acc2[r][1] = 0ull; }

    for (int kt = 0; kt < IN_F; kt += 32) {
        const float4* Wg = reinterpret_cast<const float4*>(W + kt * OUT_F);
        float4* Wsv = reinterpret_cast<float4*>(Ws);
#pragma unroll
        for (int i = 0; i < 4; i++) Wsv[tid + 256 * i] = Wg[tid + 256 * i];

#pragma unroll
        for (int i = 0; i < 2; i++) {
            int idx = tid + 256 * i;
            int r = idx >> 3;
            int cc = (idx & 7) * 4;
            int gr = row0 + r;
            float4 v = make_float4(0.f, 0.f, 0.f, 0.f);
            if (gr < N_NODES)
                v = *reinterpret_cast<const float4*>(h + (size_t)gr * IN_F + kt + cc);
            *reinterpret_cast<float4*>(&hs[r][cc]) = v;
        }
        __syncthreads();

#pragma unroll
        for (int k = 0; k < 32; k++) {
            float4 w = *reinterpret_cast<const float4*>(Ws + k * 128 + tx * 4);
            unsigned long long w01 = pk2(w.x, w.y);
            unsigned long long w23 = pk2(w.z, w.w);
#pragma unroll
            for (int r = 0; r < 8; r++) {
                float hv = hs[ty * 8 + r][k];
                unsigned long long h2 = pk2(hv, hv);
                acc2[r][0] = fma2(h2, w01, acc2[r][0]);
                acc2[r][1] = fma2(h2, w23, acc2[r][1]);
            }
        }
        __syncthreads();
    }

    float4 a1 = *reinterpret_cast<const float4*>(a + tx * 4);
    float4 a2 = *reinterpret_cast<const float4*>(a + OUT_F + tx * 4);

#pragma unroll
    for (int r = 0; r < 8; r++) {
        int gr = row0 + ty * 8 + r;
        float4 v;
        upk2(acc2[r][0], v.x, v.y);
        upk2(acc2[r][1], v.z, v.w);
        float p1 = v.x * a1.x + v.y * a1.y + v.z * a1.z + v.w * a1.w;
        float p2 = v.x * a2.x + v.y * a2.y + v.z * a2.z + v.w * a2.w;
#pragma unroll
        for (int off = 16; off > 0; off >>= 1) {
            p1 += __shfl_xor_sync(0xFFFFFFFFu, p1, off);
            p2 += __shfl_xor_sync(0xFFFFFFFFu, p2, off);
        }
        if (gr < N_NODES) {
            __half2 h01 = __floats2half2_rn(v.x, v.y);
            __half2 h23 = __floats2half2_rn(v.z, v.w);
            uint2 pk;
            pk.x = *reinterpret_cast<unsigned*>(&h01);
            pk.y = *reinterpret_cast<unsigned*>(&h23);
            *reinterpret_cast<uint2*>(g_Wh + (size_t)gr * OUT_F + tx * 4) = pk;
            if (tx == 0) { g_s1[gr] = p1; g_s2[gr] = p2; }
        }
    }
}

// ---------------- K2: zero histogram ----------------
__global__ void zero_cnt_kernel()
{
    int i = blockIdx.x * blockDim.x + threadIdx.x;
    if (i < N_NODES) g_cnt[i] = 0;
}

// ---------------- K3: histogram of rows ----------------
__global__ __launch_bounds__(256) void hist_kernel(const int* __restrict__ ei)
{
    int i = blockIdx.x * blockDim.x + threadIdx.x;
    if (i >= N_EDGES) return;
    atomicAdd(&g_cnt[ei[i]], 1);
}

// ---------------- K4a: per-block reduce of cnt -> bsum ----------------
__global__ __launch_bounds__(SCAN_BLK) void scan_reduce_kernel()
{
    __shared__ int sh[SCAN_BLK / 32];
    int i = blockIdx.x * SCAN_BLK + threadIdx.x;
    int v = (i < N_NODES) ? g_cnt[i] : 0;
#pragma unroll
    for (int o = 16; o > 0; o >>= 1) v += __shfl_xor_sync(0xFFFFFFFFu, v, o);
    if ((threadIdx.x & 31) == 0) sh[threadIdx.x >> 5] = v;
    __syncthreads();
    if (threadIdx.x < SCAN_BLK / 32) {
        int s = sh[threadIdx.x];
#pragma unroll
        for (int o = SCAN_BLK / 64; o > 0; o >>= 1) s += __shfl_xor_sync(0xFFFFFFFFu, s, o);
        if (threadIdx.x == 0) g_bsum[blockIdx.x] = s;
    }
}

// ---------------- K4b: scan block sums (1 block) ----------------
__global__ __launch_bounds__(SCAN_BLK) void scan_top_kernel()
{
    __shared__ int sh[SCAN_BLK];
    int t = threadIdx.x;
    int v = (t < SCAN_NB) ? g_bsum[t] : 0;
    sh[t] = v;
    __syncthreads();
#pragma unroll
    for (int o = 1; o < SCAN_BLK; o <<= 1) {
        int x = (t >= o) ? sh[t - o] : 0;
        __syncthreads();
        sh[t] += x;
        __syncthreads();
    }
    if (t < SCAN_NB) g_bbase[t] = sh[t] - v;   // exclusive
    if (t == SCAN_BLK - 1) g_rowptr[N_NODES] = sh[SCAN_BLK - 1];
}

// ---------------- K4c: per-block exclusive scan + base -> rowptr/cursor ----------------
__global__ __launch_bounds__(SCAN_BLK) void scan_down_kernel()
{
    __shared__ int sh[SCAN_BLK];
    int t = threadIdx.x;
    int i = blockIdx.x * SCAN_BLK + t;
    int v = (i < N_NODES) ? g_cnt[i] : 0;
    sh[t] = v;
    __syncthreads();
#pragma unroll
    for (int o = 1; o < SCAN_BLK; o <<= 1) {
        int x = (t >= o) ? sh[t - o] : 0;
        __syncthreads();
        sh[t] += x;
        __syncthreads();
    }
    if (i < N_NODES) {
        int p = g_bbase[blockIdx.x] + sh[t] - v;
        g_rowptr[i] = p;
        g_cursor[i] = p;
    }
}

// ---------------- K5: scatter edges into row-sorted order; compute e ----------------
__global__ __launch_bounds__(256) void scatter_kernel(const int* __restrict__ ei)
{
    int i = blockIdx.x * blockDim.x + threadIdx.x;
    if (i >= N_EDGES) return;
    int r = ei[i];
    int c = ei[N_EDGES + i];
    float e = g_s1[r] + g_s2[c];
    e = (e > 0.0f) ? e : ALPHA * e;
    int pos = atomicAdd(&g_cursor[r], 1);
    g_ec[pos] = make_float2(e, __int_as_float(c));
}

// ---------------- K6: fused per-row softmax + gather-aggregate (warp per row) ----------------
__global__ __launch_bounds__(256) void row_kernel(float* __restrict__ out)
{
    int r = (blockIdx.x * blockDim.x + threadIdx.x) >> 5;
    if (r >= N_NODES) return;
    int lane = threadIdx.x & 31;
    int start = g_rowptr[r];
    int end   = g_rowptr[r + 1];

    // pass 1: rowsum
    float s = 0.0f;
    for (int j = start + lane; j < end; j += 32) s += g_ec[j].x;
#pragma unroll
    for (int o = 16; o > 0; o >>= 1) s += __shfl_xor_sync(0xFFFFFFFFu, s, o);
    float rowsum = s;

    // pass 2: expsum
    float es = 0.0f;
    for (int j = start + lane; j < end; j += 32) es += __expf(g_ec[j].x - rowsum);
#pragma unroll
    for (int o = 16; o > 0; o >>= 1) es += __shfl_xor_sync(0xFFFFFFFFu, es, o);
    float inv = 1.0f / (es + EPS);

    // pass 3: gather-aggregate (fp16 Wh, fp32 accumulate)
    float4 acc = make_float4(0.f, 0.f, 0.f, 0.f);
    for (int base = start; base < end; base += 32) {
        int idx = base + lane;
        float att = 0.0f;
        int col = 0;
        if (idx < end) {
            float2 ec = g_ec[idx];
            att = __expf(ec.x - rowsum) * inv;
            col = __float_as_int(ec.y);
        }
        int m = min(32, end - base);
#pragma unroll 4
        for (int j = 0; j < m; j++) {
            float aj = __shfl_sync(0xFFFFFFFFu, att, j);
            int   cj = __shfl_sync(0xFFFFFFFFu, col, j);
            uint2 pv = *reinterpret_cast<const uint2*>(g_Wh + (size_t)cj * OUT_F + lane * 4);
            __half2 h01 = *reinterpret_cast<__half2*>(&pv.x);
            __half2 h23 = *reinterpret_cast<__half2*>(&pv.y);
            float2 f01 = __half22float2(h01);
            float2 f23 = __half22float2(h23);
            acc.x += aj * f01.x;
            acc.y += aj * f01.y;
            acc.z += aj * f23.x;
            acc.w += aj * f23.y;
        }
    }
    *reinterpret_cast<float4*>(out + (size_t)r * OUT_F + lane * 4) = acc;
}

// ---------------- launch ----------------
extern "C" void kernel_launch(void* const* d_in, const int* in_sizes, int n_in,
                              void* d_out, int out_size)
{
    const float* h  = (const float*)d_in[0];
    const int*   ei = (const int*)d_in[1];
    const float* W  = (const float*)d_in[2];
    const float* a  = (const float*)d_in[3];
    float* out = (float*)d_out;

    gat_gemm_kernel<<<(N_NODES + 63) / 64, 256>>>(h, W, a);

    zero_cnt_kernel<<<(N_NODES + 255) / 256, 256>>>();
    hist_kernel<<<(N_EDGES + 255) / 256, 256>>>(ei);
    scan_reduce_kernel<<<SCAN_NB, SCAN_BLK>>>();
    scan_top_kernel<<<1, SCAN_BLK>>>();
    scan_down_kernel<<<SCAN_NB, SCAN_BLK>>>();
    scatter_kernel<<<(N_EDGES + 255) / 256, 256>>>(ei);

    row_kernel<<<(N_NODES * 32 + 255) / 256, 256>>>(out);
}

// round 10
// speedup vs baseline: 1.8100x; 1.0105x over previous
#include <cuda_runtime.h>
#include <cuda_fp16.h>
#include <cuda_bf16.h>
#include <cstdint>

#define N_NODES 50000
#define IN_F 128
#define OUT_F 128
#define N_EDGES 800000
#define ALPHA 0.2f
#define EPS 1e-16f

#define SCAN_BLK 256
#define SCAN_NB ((N_NODES + SCAN_BLK - 1) / SCAN_BLK)   // 196

// ---------------- device scratch (static, no allocation) ----------------
__device__ __align__(16) __half g_Wh[(size_t)N_NODES * OUT_F];   // 12.8 MB (fp16)
__device__ float g_s1[N_NODES];
__device__ float g_s2[N_NODES];
__device__ int   g_cnt[N_NODES];
__device__ unsigned g_look[SCAN_NB];   // decoupled-lookback: (sum<<2) | status (0=inv,1=agg,2=prefix)
__device__ int   g_rowptr[N_NODES + 1];
__device__ int   g_cursor[N_NODES];
__device__ __align__(8) float2 g_ec[N_EDGES];  // .x = e (lrelu score), .y = bitcast(col)

// ---------------- f32x2 packed helpers ----------------
__device__ __forceinline__ unsigned long long pk2(float lo, float hi) {
    unsigned long long r;
    asm("mov.b64 %0, {%1, %2};" : "=l"(r) : "f"(lo), "f"(hi));
    return r;
}
__device__ __forceinline__ void upk2(unsigned long long p, float& lo, float& hi) {
    asm("mov.b64 {%0, %1}, %2;" : "=f"(lo), "=f"(hi) : "l"(p));
}
__device__ __forceinline__ unsigned long long fma2(unsigned long long a,
                                                   unsigned long long b,
                                                   unsigned long long c) {
    unsigned long long d;
    asm("fma.rn.f32x2 %0, %1, %2, %3;" : "=l"(d) : "l"(a), "l"(b), "l"(c));
    return d;
}
__device__ __forceinline__ unsigned ldv_u32(const unsigned* p) {
    unsigned v;
    asm volatile("ld.global.volatile.u32 %0, [%1];" : "=r"(v) : "l"(p));
    return v;
}

// ---------------- K1: Wh = h @ W (f32x2), fused s1/s2 epilogue, fp16 store ----------------
__global__ __launch_bounds__(256) void gat_gemm_kernel(
    const float* __restrict__ h, const float* __restrict__ W,
    const float* __restrict__ a)
{
    __shared__ float hs[64][36];
    __shared__ float Ws[32 * 128];

    const int tid = threadIdx.x;
    const int tx = tid & 31;
    const int ty = tid >> 5;
    const int row0 = blockIdx.x * 64;

    unsigned long long acc2[8][2];
#pragma unroll
    for (int r = 0; r < 8; r++) { acc2[r][0] = 0ull; acc2[r][1] = 0ull; }

    for (int kt = 0; kt < IN_F; kt += 32) {
        const float4* Wg = reinterpret_cast<const float4*>(W + kt * OUT_F);
        float4* Wsv = reinterpret_cast<float4*>(Ws);
#pragma unroll
        for (int i = 0; i < 4; i++) Wsv[tid + 256 * i] = Wg[tid + 256 * i];

#pragma unroll
        for (int i = 0; i < 2; i++) {
            int idx = tid + 256 * i;
            int r = idx >> 3;
            int cc = (idx & 7) * 4;
            int gr = row0 + r;
            float4 v = make_float4(0.f, 0.f, 0.f, 0.f);
            if (gr < N_NODES)
                v = *reinterpret_cast<const float4*>(h + (size_t)gr * IN_F + kt + cc);
            *reinterpret_cast<float4*>(&hs[r][cc]) = v;
        }
        __syncthreads();

#pragma unroll
        for (int k = 0; k < 32; k++) {
            float4 w = *reinterpret_cast<const float4*>(Ws + k * 128 + tx * 4);
            unsigned long long w01 = pk2(w.x, w.y);
            unsigned long long w23 = pk2(w.z, w.w);
#pragma unroll
            for (int r = 0; r < 8; r++) {
                float hv = hs[ty * 8 + r][k];
                unsigned long long h2 = pk2(hv, hv);
                acc2[r][0] = fma2(h2, w01, acc2[r][0]);
                acc2[r][1] = fma2(h2, w23, acc2[r][1]);
            }
        }
        __syncthreads();
    }

    float4 a1 = *reinterpret_cast<const float4*>(a + tx * 4);
    float4 a2 = *reinterpret_cast<const float4*>(a + OUT_F + tx * 4);

#pragma unroll
    for (int r = 0; r < 8; r++) {
        int gr = row0 + ty * 8 + r;
        float4 v;
        upk2(acc2[r][0], v.x, v.y);
        upk2(acc2[r][1], v.z, v.w);
        float p1 = v.x * a1.x + v.y * a1.y + v.z * a1.z + v.w * a1.w;
        float p2 = v.x * a2.x + v.y * a2.y + v.z * a2.z + v.w * a2.w;
#pragma unroll
        for (int off = 16; off > 0; off >>= 1) {
            p1 += __shfl_xor_sync(0xFFFFFFFFu, p1, off);
            p2 += __shfl_xor_sync(0xFFFFFFFFu, p2, off);
        }
        if (gr < N_NODES) {
            __half2 h01 = __floats2half2_rn(v.x, v.y);
            __half2 h23 = __floats2half2_rn(v.z, v.w);
            uint2 pk;
            pk.x = *reinterpret_cast<unsigned*>(&h01);
            pk.y = *reinterpret_cast<unsigned*>(&h23);
            *reinterpret_cast<uint2*>(g_Wh + (size_t)gr * OUT_F + tx * 4) = pk;
            if (tx == 0) { g_s1[gr] = p1; g_s2[gr] = p2; }
        }
    }
}

// ---------------- K2: zero histogram + lookback state ----------------
__global__ void zero_cnt_kernel()
{
    int i = blockIdx.x * blockDim.x + threadIdx.x;
    if (i < N_NODES) g_cnt[i] = 0;
    if (i < SCAN_NB) g_look[i] = 0u;   // status = invalid
    if (i == 0) g_rowptr[N_NODES] = N_EDGES;
}

// ---------------- K3: histogram of rows ----------------
__global__ __launch_bounds__(256) void hist_kernel(const int* __restrict__ ei)
{
    int i = blockIdx.x * blockDim.x + threadIdx.x;
    if (i >= N_EDGES) return;
    atomicAdd(&g_cnt[ei[i]], 1);
}

// ---------------- K4: single-pass decoupled-lookback exclusive scan ----------------
__global__ __launch_bounds__(SCAN_BLK) void scan_lookback_kernel()
{
    __shared__ int sh[SCAN_BLK];
    __shared__ int s_excl;
    const int t = threadIdx.x;
    const int bid = blockIdx.x;
    const int i = bid * SCAN_BLK + t;

    int v = (i < N_NODES) ? g_cnt[i] : 0;
    sh[t] = v;
    __syncthreads();
#pragma unroll
    for (int o = 1; o < SCAN_BLK; o <<= 1) {
        int x = (t >= o) ? sh[t - o] : 0;
        __syncthreads();
        sh[t] += x;
        __syncthreads();
    }
    int incl = sh[t];
    int total = sh[SCAN_BLK - 1];

    // publish aggregate ASAP (packed word: value<<2 | status; relaxed atomics OK)
    if (t == 0)
        atomicExch(&g_look[bid], ((unsigned)total << 2) | 1u);

    // warp 0: warp-parallel lookback
    if (t < 32) {
        int lane = t;
        int excl = 0;
        int lb = bid - 1;
        while (true) {
            int idx = lb - lane;
            unsigned w;
            do {
                w = (idx >= 0) ? ldv_u32(&g_look[idx]) : 2u;  // beyond start: prefix 0
            } while (__any_sync(0xFFFFFFFFu, (w & 3u) == 0u));
            unsigned m = __ballot_sync(0xFFFFFFFFu, (w & 3u) == 2u);
            if (m) {
                int lp = __ffs(m) - 1;                 // nearest prefix
                int c = (lane <= lp) ? (int)(w >> 2) : 0;
#pragma unroll
                for (int o = 16; o > 0; o >>= 1) c += __shfl_xor_sync(0xFFFFFFFFu, c, o);
                excl += c;
                break;
            } else {
                int c = (int)(w >> 2);
#pragma unroll
                for (int o = 16; o > 0; o >>= 1) c += __shfl_xor_sync(0xFFFFFFFFu, c, o);
                excl += c;
                lb -= 32;
            }
        }
        if (lane == 0) {
            atomicExch(&g_look[bid], ((unsigned)(excl + total) << 2) | 2u);
            s_excl = excl;
        }
    }
    __syncthreads();

    if (i < N_NODES) {
        int p = s_excl + incl - v;   // exclusive prefix
        g_rowptr[i] = p;
        g_cursor[i] = p;
    }
}

// ---------------- K5: scatter edges into row-sorted order; compute e ----------------
__global__ __launch_bounds__(256) void scatter_kernel(const int* __restrict__ ei)
{
    int i = blockIdx.x * blockDim.x + threadIdx.x;
    if (i >= N_EDGES) return;
    int r = ei[i];
    int c = ei[N_EDGES + i];
    float e = g_s1[r] + g_s2[c];
    e = (e > 0.0f) ? e : ALPHA * e;
    int pos = atomicAdd(&g_cursor[r], 1);
    g_ec[pos] = make_float2(e, __int_as_float(c));
}

// ---------------- K6: fused per-row softmax + gather-aggregate (warp per row) ----------------
__global__ __launch_bounds__(256) void row_kernel(float* __restrict__ out)
{
    int r = (blockIdx.x * blockDim.x + threadIdx.x) >> 5;
    if (r >= N_NODES) return;
    int lane = threadIdx.x & 31;
    int start = g_rowptr[r];
    int end   = g_rowptr[r + 1];

    // pass 1: rowsum
    float s = 0.0f;
    for (int j = start + lane; j < end; j += 32) s += g_ec[j].x;
#pragma unroll
    for (int o = 16; o > 0; o >>= 1) s += __shfl_xor_sync(0xFFFFFFFFu, s, o);
    float rowsum = s;

    // pass 2: expsum
    float es = 0.0f;
    for (int j = start + lane; j < end; j += 32) es += __expf(g_ec[j].x - rowsum);
#pragma unroll
    for (int o = 16; o > 0; o >>= 1) es += __shfl_xor_sync(0xFFFFFFFFu, es, o);
    float inv = 1.0f / (es + EPS);

    // pass 3: gather-aggregate (fp16 Wh, fp32 accumulate)
    float4 acc = make_float4(0.f, 0.f, 0.f, 0.f);
    for (int base = start; base < end; base += 32) {
        int idx = base + lane;
        float att = 0.0f;
        int col = 0;
        if (idx < end) {
            float2 ec = g_ec[idx];
            att = __expf(ec.x - rowsum) * inv;
            col = __float_as_int(ec.y);
        }
        int m = min(32, end - base);
#pragma unroll 4
        for (int j = 0; j < m; j++) {
            float aj = __shfl_sync(0xFFFFFFFFu, att, j);
            int   cj = __shfl_sync(0xFFFFFFFFu, col, j);
            uint2 pv = *reinterpret_cast<const uint2*>(g_Wh + (size_t)cj * OUT_F + lane * 4);
            __half2 h01 = *reinterpret_cast<__half2*>(&pv.x);
            __half2 h23 = *reinterpret_cast<__half2*>(&pv.y);
            float2 f01 = __half22float2(h01);
            float2 f23 = __half22float2(h23);
            acc.x += aj * f01.x;
            acc.y += aj * f01.y;
            acc.z += aj * f23.x;
            acc.w += aj * f23.y;
        }
    }
    *reinterpret_cast<float4*>(out + (size_t)r * OUT_F + lane * 4) = acc;
}

// ---------------- launch ----------------
extern "C" void kernel_launch(void* const* d_in, const int* in_sizes, int n_in,
                              void* d_out, int out_size)
{
    const float* h  = (const float*)d_in[0];
    const int*   ei = (const int*)d_in[1];
    const float* W  = (const float*)d_in[2];
    const float* a  = (const float*)d_in[3];
    float* out = (float*)d_out;

    gat_gemm_kernel<<<(N_NODES + 63) / 64, 256>>>(h, W, a);

    zero_cnt_kernel<<<(N_NODES + 255) / 256, 256>>>();
    hist_kernel<<<(N_EDGES + 255) / 256, 256>>>(ei);
    scan_lookback_kernel<<<SCAN_NB, SCAN_BLK>>>();
    scatter_kernel<<<(N_EDGES + 255) / 256, 256>>>(ei);

    row_kernel<<<(N_NODES * 32 + 255) / 256, 256>>>(out);
}